// round 1
// baseline (speedup 1.0000x reference)
#include <cuda_runtime.h>

#define BTDIM 48
#define NN 1024
#define FF 64
#define EM 16
#define TI 64
#define TJ 32

// Scratch (device globals: allocation-free per harness rules)
__device__ __align__(16) float g_Wh[BTDIM * NN * FF];   // 12.6 MB
__device__ float g_u[BTDIM * NN];
__device__ float g_v[BTDIM * NN];
__device__ float g_f1[NN];
__device__ float g_f2[NN];

// ---------------------------------------------------------------------------
// f1[i] = emb1[i,:]·a2[:16],  f2[i] = emb2[i,:]·a2[16:]
__global__ void k_f12(const float* __restrict__ emb1,
                      const float* __restrict__ emb2,
                      const float* __restrict__ a2) {
    int i = blockIdx.x * blockDim.x + threadIdx.x;
    if (i < NN) {
        float s1 = 0.f, s2 = 0.f;
#pragma unroll
        for (int m = 0; m < EM; m++) {
            s1 += emb1[i * EM + m] * a2[m];
            s2 += emb2[i * EM + m] * a2[EM + m];
        }
        g_f1[i] = s1;
        g_f2[i] = s2;
    }
}

// ---------------------------------------------------------------------------
// Wh = x @ W : 64 rows per block, W and x tile staged in smem.
__global__ void k_wh(const float* __restrict__ x, const float* __restrict__ W) {
    __shared__ __align__(16) float Ws[64 * 64];
    __shared__ __align__(16) float xs[64 * 64];
    int tid = threadIdx.x;
    int row0 = blockIdx.x * 64;

    const float4* W4 = (const float4*)W;
    float4* Ws4 = (float4*)Ws;
#pragma unroll
    for (int k = 0; k < 4; k++) Ws4[tid + 256 * k] = W4[tid + 256 * k];

    const float4* x4 = (const float4*)(x + (size_t)row0 * 64);
    float4* xs4 = (float4*)xs;
#pragma unroll
    for (int k = 0; k < 4; k++) xs4[tid + 256 * k] = x4[tid + 256 * k];
    __syncthreads();

    int f = tid & 63;
    int rb = tid >> 6;  // 0..3 ; thread handles rows rb, rb+4, ..., rb+60
    float acc[16];
#pragma unroll
    for (int r = 0; r < 16; r++) acc[r] = 0.f;

#pragma unroll 4
    for (int k = 0; k < 64; k++) {
        float w = Ws[k * 64 + f];
#pragma unroll
        for (int r = 0; r < 16; r++)
            acc[r] += xs[(rb + 4 * r) * 64 + k] * w;
    }
#pragma unroll
    for (int r = 0; r < 16; r++)
        g_Wh[(size_t)(row0 + rb + 4 * r) * 64 + f] = acc[r];
}

// ---------------------------------------------------------------------------
// u[row] = Wh[row,:]·a[0:64] + f1[i] ; v[row] = Wh[row,:]·a[64:128] + f2[i]
// one warp per row
__global__ void k_uv(const float* __restrict__ a) {
    int row = blockIdx.x * 8 + (threadIdx.x >> 5);
    int lane = threadIdx.x & 31;
    const float* wh = g_Wh + (size_t)row * 64;
    float w0 = wh[lane], w1 = wh[lane + 32];
    float u = w0 * a[lane] + w1 * a[lane + 32];
    float v = w0 * a[64 + lane] + w1 * a[96 + lane];
#pragma unroll
    for (int o = 16; o; o >>= 1) {
        u += __shfl_xor_sync(0xFFFFFFFFu, u, o);
        v += __shfl_xor_sync(0xFFFFFFFFu, v, o);
    }
    if (lane == 0) {
        int i = row & (NN - 1);
        g_u[row] = u + g_f1[i];
        g_v[row] = v + g_f2[i];
    }
}

// ---------------------------------------------------------------------------
// Fused masked-softmax attention + att@Wh + ELU.
// Block: 256 threads, handles one bt and TI=64 rows i.
__global__ void k_att(const int* __restrict__ adj, float* __restrict__ out) {
    __shared__ float sv[NN];
    __shared__ float su[TI], smx[TI], sl[TI];
    __shared__ __align__(16) float whs[TJ * 64];
    __shared__ float ps[TI * 33];  // pitch 33: conflict-free

    int bt = blockIdx.y;
    int i0 = blockIdx.x * TI;
    int tid = threadIdx.x;

#pragma unroll
    for (int k = 0; k < 4; k++)
        sv[tid + 256 * k] = g_v[bt * NN + tid + 256 * k];
    if (tid < TI) su[tid] = g_u[bt * NN + i0 + tid];
    __syncthreads();

    // ---- Phase 1: per-row masked max + exp-sum (two-pass, one exp/element)
    int w = tid >> 5, lane = tid & 31;
    for (int r = 0; r < 8; r++) {
        int ii = w * 8 + r;
        float u = su[ii];
        const int* arow = adj + (size_t)(i0 + ii) * NN;
        float mx = -1e30f;
        for (int j = lane; j < NN; j += 32) {
            if (arow[j] > 0) {
                float sc = u + sv[j];
                sc = fmaxf(sc, 0.2f * sc);  // LeakyReLU (monotone form)
                mx = fmaxf(mx, sc);
            }
        }
#pragma unroll
        for (int o = 16; o; o >>= 1)
            mx = fmaxf(mx, __shfl_xor_sync(0xFFFFFFFFu, mx, o));
        float s = 0.f;
        for (int j = lane; j < NN; j += 32) {
            if (arow[j] > 0) {
                float sc = u + sv[j];
                sc = fmaxf(sc, 0.2f * sc);
                s += __expf(sc - mx);
            }
        }
#pragma unroll
        for (int o = 16; o; o >>= 1)
            s += __shfl_xor_sync(0xFFFFFFFFu, s, o);
        if (lane == 0) {
            smx[ii] = mx;
            sl[ii] = (s > 0.f) ? s : 1.f;
        }
    }
    __syncthreads();

    // ---- Phase 2: out[i,f] = (sum_j p(i,j)*Wh[j,f]) / l[i], 64x64 per block
    int tx = tid & 15, ty = tid >> 4;  // f-group, i-group
    float acc[4][4];
#pragma unroll
    for (int r = 0; r < 4; r++)
#pragma unroll
        for (int c = 0; c < 4; c++) acc[r][c] = 0.f;

    const float4* Wh4 = (const float4*)(g_Wh + (size_t)bt * NN * 64);
    float4* whs4 = (float4*)whs;

    for (int j0 = 0; j0 < NN; j0 += TJ) {
        // stage Wh tile [TJ x 64] (contiguous 2048 floats)
        whs4[tid] = Wh4[j0 * 16 + tid];
        whs4[tid + 256] = Wh4[j0 * 16 + tid + 256];
        // build p tile [TI x TJ]
#pragma unroll
        for (int k = 0; k < 8; k++) {
            int e = tid + 256 * k;
            int ii = e >> 5, jj = e & 31;
            int j = j0 + jj;
            float p = 0.f;
            if (adj[(size_t)(i0 + ii) * NN + j] > 0) {
                float sc = su[ii] + sv[j];
                sc = fmaxf(sc, 0.2f * sc);
                p = __expf(sc - smx[ii]);
            }
            ps[ii * 33 + jj] = p;
        }
        __syncthreads();
#pragma unroll
        for (int jj = 0; jj < TJ; jj++) {
            float4 wv = whs4[jj * 16 + tx];
#pragma unroll
            for (int r = 0; r < 4; r++) {
                float p = ps[(ty * 4 + r) * 33 + jj];
                acc[r][0] += p * wv.x;
                acc[r][1] += p * wv.y;
                acc[r][2] += p * wv.z;
                acc[r][3] += p * wv.w;
            }
        }
        __syncthreads();
    }

    // ---- Epilogue: normalize + ELU + store
#pragma unroll
    for (int r = 0; r < 4; r++) {
        int ii = ty * 4 + r;
        float inv = 1.f / sl[ii];
        float4 o;
        float t;
        t = acc[r][0] * inv; o.x = (t > 0.f) ? t : (__expf(t) - 1.f);
        t = acc[r][1] * inv; o.y = (t > 0.f) ? t : (__expf(t) - 1.f);
        t = acc[r][2] * inv; o.z = (t > 0.f) ? t : (__expf(t) - 1.f);
        t = acc[r][3] * inv; o.w = (t > 0.f) ? t : (__expf(t) - 1.f);
        ((float4*)(out + ((size_t)(bt * NN + i0 + ii)) * 64))[tx] = o;
    }
}

// ---------------------------------------------------------------------------
extern "C" void kernel_launch(void* const* d_in, const int* in_sizes, int n_in,
                              void* d_out, int out_size) {
    const float* x    = (const float*)d_in[0];
    const int*   adj  = (const int*)d_in[1];
    const float* emb1 = (const float*)d_in[2];
    const float* emb2 = (const float*)d_in[3];
    const float* W    = (const float*)d_in[4];
    const float* a    = (const float*)d_in[5];
    const float* a2   = (const float*)d_in[6];
    float* out = (float*)d_out;

    k_f12<<<4, 256>>>(emb1, emb2, a2);
    k_wh<<<BTDIM * NN / 64, 256>>>(x, W);
    k_uv<<<BTDIM * NN / 8, 256>>>(a);
    dim3 g(NN / TI, BTDIM);
    k_att<<<g, 256>>>(adj, out);
}

// round 3
// speedup vs baseline: 2.3629x; 2.3629x over previous
#include <cuda_runtime.h>
#include <cuda_bf16.h>
#include <cstdint>

#define BT 48
#define NN 1024
#define FF 64

// ---------------------------------------------------------------- helpers
__device__ __forceinline__ uint32_t smem_to_u32(const void* p) {
    uint32_t a;
    asm("{ .reg .u64 t; cvta.to.shared.u64 t, %1; cvt.u32.u64 %0, t; }" : "=r"(a) : "l"(p));
    return a;
}
__device__ __forceinline__ void ldsm_x4(uint32_t& r0, uint32_t& r1, uint32_t& r2, uint32_t& r3,
                                        uint32_t addr) {
    asm volatile("ldmatrix.sync.aligned.m8n8.x4.shared.b16 {%0,%1,%2,%3}, [%4];"
                 : "=r"(r0), "=r"(r1), "=r"(r2), "=r"(r3) : "r"(addr));
}
__device__ __forceinline__ void mma_bf16(float* c, uint32_t a0, uint32_t a1, uint32_t a2,
                                         uint32_t a3, uint32_t b0, uint32_t b1) {
    asm volatile(
        "mma.sync.aligned.m16n8k16.row.col.f32.bf16.bf16.f32 "
        "{%0,%1,%2,%3}, {%4,%5,%6,%7}, {%8,%9}, {%0,%1,%2,%3};"
        : "+f"(c[0]), "+f"(c[1]), "+f"(c[2]), "+f"(c[3])
        : "r"(a0), "r"(a1), "r"(a2), "r"(a3), "r"(b0), "r"(b1));
}
#define SWZ(off) ((off) ^ (((off) >> 3) & 0x70))

// ---------------------------------------------------------------- globals
__device__ __align__(16) float g_Wh[BT * NN * FF];
__device__ __align__(16) __nv_bfloat16 g_Bh[BT * FF * NN];  // Wh^T hi  (n=f major, k=j)
__device__ __align__(16) __nv_bfloat16 g_Bl[BT * FF * NN];  // Wh^T lo
__device__ float g_Eu[BT * NN], g_Fu[BT * NN], g_Ev[BT * NN], g_Fv[BT * NN];
__device__ float g_f1[NN], g_f2[NN];
__device__ unsigned g_adjbits[NN * NN / 32];

// ---------------------------------------------------------------- prep kernels
__global__ void k_f12(const float* __restrict__ emb1, const float* __restrict__ emb2,
                      const float* __restrict__ a2) {
    int i = blockIdx.x * blockDim.x + threadIdx.x;
    if (i < NN) {
        float s1 = 0.f, s2 = 0.f;
#pragma unroll
        for (int m = 0; m < 16; m++) {
            s1 += emb1[i * 16 + m] * a2[m];
            s2 += emb2[i * 16 + m] * a2[16 + m];
        }
        g_f1[i] = s1;
        g_f2[i] = s2;
    }
}

__global__ void k_pack(const int* __restrict__ adj) {
    int gw = (blockIdx.x * blockDim.x + threadIdx.x) >> 5;
    int lane = threadIdx.x & 31;
    int val = adj[(size_t)gw * 32 + lane] > 0;
    unsigned m = __ballot_sync(0xFFFFFFFFu, val);
    if (lane == 0) g_adjbits[gw] = m;
}

__global__ void k_wh(const float* __restrict__ x, const float* __restrict__ W) {
    __shared__ __align__(16) float Ws[64 * 64];
    __shared__ __align__(16) float xs[64 * 64];
    int tid = threadIdx.x;
    int row0 = blockIdx.x * 64;
    const float4* W4 = (const float4*)W;
    float4* Ws4 = (float4*)Ws;
#pragma unroll
    for (int k = 0; k < 4; k++) Ws4[tid + 256 * k] = W4[tid + 256 * k];
    const float4* x4 = (const float4*)(x + (size_t)row0 * 64);
    float4* xs4 = (float4*)xs;
#pragma unroll
    for (int k = 0; k < 4; k++) xs4[tid + 256 * k] = x4[tid + 256 * k];
    __syncthreads();
    int f = tid & 63, rb = tid >> 6;
    float acc[16];
#pragma unroll
    for (int r = 0; r < 16; r++) acc[r] = 0.f;
#pragma unroll 4
    for (int k = 0; k < 64; k++) {
        float w = Ws[k * 64 + f];
#pragma unroll
        for (int r = 0; r < 16; r++) acc[r] += xs[(rb + 4 * r) * 64 + k] * w;
    }
#pragma unroll
    for (int r = 0; r < 16; r++) g_Wh[(size_t)(row0 + rb + 4 * r) * 64 + f] = acc[r];
}

__global__ void k_exp(const float* __restrict__ a) {
    int row = blockIdx.x * 8 + (threadIdx.x >> 5);
    int lane = threadIdx.x & 31;
    const float* wh = g_Wh + (size_t)row * 64;
    float w0 = wh[lane], w1 = wh[lane + 32];
    float u = w0 * a[lane] + w1 * a[lane + 32];
    float v = w0 * a[64 + lane] + w1 * a[96 + lane];
#pragma unroll
    for (int o = 16; o; o >>= 1) {
        u += __shfl_xor_sync(0xFFFFFFFFu, u, o);
        v += __shfl_xor_sync(0xFFFFFFFFu, v, o);
    }
    if (lane == 0) {
        int i = row & (NN - 1);
        u += g_f1[i];
        v += g_f2[i];
        g_Eu[row] = __expf(u);
        g_Fu[row] = __expf(0.2f * u);
        g_Ev[row] = __expf(v);
        g_Fv[row] = __expf(0.2f * v);
    }
}

// Transpose + split Wh -> bf16 hi/lo: B[bt][f][j] = Wh[bt][j][f]
__global__ void k_split() {
    __shared__ float ts[64][65];
    int tid = threadIdx.x;
    int bt = blockIdx.y, j0 = blockIdx.x * 64;
#pragma unroll
    for (int kk = 0; kk < 4; kk++) {
        int idx = tid + 256 * kk;
        int r = idx >> 4, fq = idx & 15;
        float4 v = *(const float4*)&g_Wh[((size_t)bt * NN + j0 + r) * 64 + fq * 4];
        ts[r][fq * 4 + 0] = v.x;
        ts[r][fq * 4 + 1] = v.y;
        ts[r][fq * 4 + 2] = v.z;
        ts[r][fq * 4 + 3] = v.w;
    }
    __syncthreads();
#pragma unroll
    for (int kk = 0; kk < 8; kk++) {
        int pi = tid + 256 * kk;
        int f = pi >> 5, jp = pi & 31;
        float x0 = ts[2 * jp][f], x1 = ts[2 * jp + 1][f];
        __nv_bfloat16 h0 = __float2bfloat16(x0), h1 = __float2bfloat16(x1);
        float l0 = x0 - __bfloat162float(h0), l1 = x1 - __bfloat162float(h1);
        size_t off = ((size_t)(bt * 64 + f)) * NN + j0 + 2 * jp;
        *(__nv_bfloat162*)&g_Bh[off] = __halves2bfloat162(h0, h1);
        *(__nv_bfloat162*)&g_Bl[off] = __halves2bfloat162(__float2bfloat16(l0), __float2bfloat16(l1));
    }
}

// ---------------------------------------------------------------- main attention kernel
// Block = (bt, 128 i-rows). A = p tile [128x64] bf16 hi/lo; B = Wh^T [64x64] hi/lo.
// mma.sync m16n8k16, warp w owns rows 16w..16w+15, all 64 output cols.
static constexpr int OFF_AH = 0;       // 128 rows * 128B
static constexpr int OFF_AL = 16384;
static constexpr int OFF_BH = 32768;   // 64 rows * 128B
static constexpr int OFF_BL = 40960;
static constexpr int OFF_EV = 49152;   // 1024 f32
static constexpr int OFF_FV = 53248;
static constexpr int OFF_EU = 57344;   // 128 f32
static constexpr int OFF_FU = 57856;
static constexpr int OFF_SUM = 58368;  // 128 f32
static constexpr int SMEM_DYN = 58880;

__global__ void __launch_bounds__(256, 3) k_att(float* __restrict__ out) {
    extern __shared__ char sm[];
    const uint32_t sb = smem_to_u32(sm);

    const int tid = threadIdx.x;
    const int wid = tid >> 5, lane = tid & 31;
    const int bt = blockIdx.y;
    const int i0 = blockIdx.x * 128;

    float* sEv = (float*)(sm + OFF_EV);
    float* sFv = (float*)(sm + OFF_FV);
    float* sEu = (float*)(sm + OFF_EU);
    float* sFu = (float*)(sm + OFF_FU);
    float* sSum = (float*)(sm + OFF_SUM);
#pragma unroll
    for (int k = 0; k < 4; k++) {
        sEv[tid + 256 * k] = g_Ev[bt * NN + tid + 256 * k];
        sFv[tid + 256 * k] = g_Fv[bt * NN + tid + 256 * k];
    }
    if (tid < 128) {
        sEu[tid] = g_Eu[bt * NN + i0 + tid];
        sFu[tid] = g_Fu[bt * NN + i0 + tid];
    }
    __syncthreads();

    // per-lane ldmatrix addressing
    const int arow = 16 * wid + (lane & 15);
    const uint32_t aBase = (uint32_t)arow * 128 + ((lane >> 4) << 4);  // + kk*32 later
    const uint32_t aXor = (uint32_t)(arow & 7) << 4;
    const int brl = (lane & 7) | ((lane & 16) >> 1);   // local B row 0..15
    const uint32_t bKoff = (uint32_t)(lane & 8) << 1;  // 0 or 16 bytes

    const int jq = tid & 15;   // j-quad for p-build
    const int rb = tid >> 4;   // base row for p-build

    float acc[8][4];
#pragma unroll
    for (int n = 0; n < 8; n++)
#pragma unroll
        for (int c = 0; c < 4; c++) acc[n][c] = 0.f;
    float rsum[8];
#pragma unroll
    for (int k = 0; k < 8; k++) rsum[k] = 0.f;

    for (int t = 0; t < 16; t++) {
        const int j0 = t * 64;
        // ---- stage B hi/lo tiles [64 f x 64 j] bf16, swizzled
#pragma unroll
        for (int rr = 0; rr < 2; rr++) {
            int idx = tid + 256 * rr;
            int f = idx >> 3, q = idx & 7;
            uint32_t so = SWZ((uint32_t)(f * 128 + q * 16));
            const uint4* srch = (const uint4*)(g_Bh + ((size_t)(bt * 64 + f)) * NN + j0);
            const uint4* srcl = (const uint4*)(g_Bl + ((size_t)(bt * 64 + f)) * NN + j0);
            *(uint4*)(sm + OFF_BH + so) = srch[q];
            *(uint4*)(sm + OFF_BL + so) = srcl[q];
        }
        // ---- build A (p) tile [128 i x 64 j] bf16 hi/lo, swizzled
#pragma unroll
        for (int k = 0; k < 8; k++) {
            int row = rb + 16 * k;
            int i = i0 + row;
            unsigned word = g_adjbits[i * 32 + (j0 >> 5) + (jq >> 3)];
            int sh = (jq * 4) & 31;
            float Eu = sEu[row], Fu = sFu[row];
            float4 ev = *(const float4*)(sEv + j0 + jq * 4);
            float4 fv = *(const float4*)(sFv + j0 + jq * 4);
            float p0 = fmaxf(Eu * ev.x, Fu * fv.x);
            float p1 = fmaxf(Eu * ev.y, Fu * fv.y);
            float p2 = fmaxf(Eu * ev.z, Fu * fv.z);
            float p3 = fmaxf(Eu * ev.w, Fu * fv.w);
            if (!((word >> (sh + 0)) & 1)) p0 = 0.f;
            if (!((word >> (sh + 1)) & 1)) p1 = 0.f;
            if (!((word >> (sh + 2)) & 1)) p2 = 0.f;
            if (!((word >> (sh + 3)) & 1)) p3 = 0.f;
            rsum[k] += (p0 + p1) + (p2 + p3);
            __nv_bfloat16 h0 = __float2bfloat16(p0), h1 = __float2bfloat16(p1);
            __nv_bfloat16 h2 = __float2bfloat16(p2), h3 = __float2bfloat16(p3);
            float l0 = p0 - __bfloat162float(h0), l1 = p1 - __bfloat162float(h1);
            float l2 = p2 - __bfloat162float(h2), l3 = p3 - __bfloat162float(h3);
            uint32_t sw = SWZ((uint32_t)(row * 128 + jq * 8));
            __nv_bfloat162 hp0 = __halves2bfloat162(h0, h1);
            __nv_bfloat162 hp1 = __halves2bfloat162(h2, h3);
            uint2 hv = {*reinterpret_cast<uint32_t*>(&hp0), *reinterpret_cast<uint32_t*>(&hp1)};
            *(uint2*)(sm + OFF_AH + sw) = hv;
            __nv_bfloat162 lp0 = __halves2bfloat162(__float2bfloat16(l0), __float2bfloat16(l1));
            __nv_bfloat162 lp1 = __halves2bfloat162(__float2bfloat16(l2), __float2bfloat16(l3));
            uint2 lv = {*reinterpret_cast<uint32_t*>(&lp0), *reinterpret_cast<uint32_t*>(&lp1)};
            *(uint2*)(sm + OFF_AL + sw) = lv;
        }
        __syncthreads();

        // ---- tensor-core GEMM on this k-tile
#pragma unroll
        for (int kk = 0; kk < 4; kk++) {
            uint32_t aoff = (aBase + kk * 32) ^ aXor;
            uint32_t ah0, ah1, ah2, ah3, al0, al1, al2, al3;
            ldsm_x4(ah0, ah1, ah2, ah3, sb + OFF_AH + aoff);
            ldsm_x4(al0, al1, al2, al3, sb + OFF_AL + aoff);
#pragma unroll
            for (int ng = 0; ng < 4; ng++) {
                uint32_t brow = ng * 16 + brl;
                uint32_t boff = (brow * 128 + kk * 32 + bKoff) ^ ((brow & 7) << 4);
                uint32_t bh0, bh1, bh2, bh3, bl0, bl1, bl2, bl3;
                ldsm_x4(bh0, bh1, bh2, bh3, sb + OFF_BH + boff);
                ldsm_x4(bl0, bl1, bl2, bl3, sb + OFF_BL + boff);
                mma_bf16(acc[2 * ng + 0], ah0, ah1, ah2, ah3, bh0, bh1);
                mma_bf16(acc[2 * ng + 1], ah0, ah1, ah2, ah3, bh2, bh3);
                mma_bf16(acc[2 * ng + 0], ah0, ah1, ah2, ah3, bl0, bl1);
                mma_bf16(acc[2 * ng + 1], ah0, ah1, ah2, ah3, bl2, bl3);
                mma_bf16(acc[2 * ng + 0], al0, al1, al2, al3, bh0, bh1);
                mma_bf16(acc[2 * ng + 1], al0, al1, al2, al3, bh2, bh3);
            }
        }
        __syncthreads();
    }

    // ---- row sums -> smem
#pragma unroll
    for (int k = 0; k < 8; k++) {
        float s = rsum[k];
        s += __shfl_xor_sync(0xFFFFFFFFu, s, 1);
        s += __shfl_xor_sync(0xFFFFFFFFu, s, 2);
        s += __shfl_xor_sync(0xFFFFFFFFu, s, 4);
        s += __shfl_xor_sync(0xFFFFFFFFu, s, 8);
        if (jq == 0) sSum[rb + 16 * k] = s;
    }
    __syncthreads();

    // ---- epilogue: normalize + ELU + store
    {
        int r0 = 16 * wid + (lane >> 2);
        int r1 = r0 + 8;
        float s0 = sSum[r0], s1 = sSum[r1];
        float inv0 = (s0 > 0.f) ? (1.f / s0) : 0.f;
        float inv1 = (s1 > 0.f) ? (1.f / s1) : 0.f;
        float* op0 = out + ((size_t)(bt * NN + i0 + r0)) * 64 + (lane & 3) * 2;
        float* op1 = out + ((size_t)(bt * NN + i0 + r1)) * 64 + (lane & 3) * 2;
#pragma unroll
        for (int nt = 0; nt < 8; nt++) {
            float v0 = acc[nt][0] * inv0, v1 = acc[nt][1] * inv0;
            float v2 = acc[nt][2] * inv1, v3 = acc[nt][3] * inv1;
            float2 o0, o1;
            o0.x = (v0 > 0.f) ? v0 : (__expf(v0) - 1.f);
            o0.y = (v1 > 0.f) ? v1 : (__expf(v1) - 1.f);
            o1.x = (v2 > 0.f) ? v2 : (__expf(v2) - 1.f);
            o1.y = (v3 > 0.f) ? v3 : (__expf(v3) - 1.f);
            *(float2*)(op0 + nt * 8) = o0;
            *(float2*)(op1 + nt * 8) = o1;
        }
    }
}

// ---------------------------------------------------------------- launch
extern "C" void kernel_launch(void* const* d_in, const int* in_sizes, int n_in,
                              void* d_out, int out_size) {
    const float* x = (const float*)d_in[0];
    const int* adj = (const int*)d_in[1];
    const float* emb1 = (const float*)d_in[2];
    const float* emb2 = (const float*)d_in[3];
    const float* W = (const float*)d_in[4];
    const float* a = (const float*)d_in[5];
    const float* a2 = (const float*)d_in[6];
    float* out = (float*)d_out;

    static int smem_set = 0;
    if (!smem_set) {
        cudaFuncSetAttribute(k_att, cudaFuncAttributeMaxDynamicSharedMemorySize, SMEM_DYN);
        smem_set = 1;
    }

    k_f12<<<4, 256>>>(emb1, emb2, a2);
    k_pack<<<NN * NN / 32 / 8, 256>>>(adj);
    k_wh<<<BT * NN / 64, 256>>>(x, W);
    k_exp<<<BT * NN / 8, 256>>>(a);
    dim3 gs(16, BT);
    k_split<<<gs, 256>>>();
    dim3 ga(8, BT);
    k_att<<<ga, 256, SMEM_DYN>>>(out);
}